// round 15
// baseline (speedup 1.0000x reference)
#include <cuda_runtime.h>
#include <cuda_bf16.h>
#include <math.h>
#include <stdint.h>

// Problem dims (fixed)
#define BSZ  32
#define TLEN 512
#define DIN  512
#define HN   1024
#define G4H  (4*HN)   // 4096

#define WPAD 1028      // W smem row stride (floats) for recurrence
#define HQS  260       // h quarter-row stride (floats); also red batch stride
#define NBLK 128       // persistent grid size (1 CTA/SM)

// GEMM staging (bytes)
#define ABYT 16384     // As: 128 rows x 128B
#define BBYT 17408     // Bs: 32 rows x 544B (136 floats, pad 8)
#define STG  (ABYT + BBYT)

// ---------------- scratch (device globals; no allocation allowed) ----------------
__device__ float g_xg[(size_t)TLEN * BSZ * G4H];   // [T][B][4H]  256 MB
__device__ float g_hseq[(size_t)BSZ * TLEN * HN];  // [B][T][H]    64 MB
__device__ float g_Wp0[(size_t)G4H * HN];          // packed Wh0 (recurrence)
__device__ float g_Wp1[(size_t)G4H * HN];          // packed Wh1
__device__ float g_h[2][BSZ * HN];                 // ping-pong h
__device__ int   g_flag0[NBLK];                    // dataflow flags, layer 0
__device__ int   g_flag1[NBLK];                    // dataflow flags, layer 1
__device__ float g_Atf[(size_t)16384 * 1024];      // tf32-rounded A   64 MB
__device__ float g_Btf[(size_t)1024 * G4H];        // tf32-rounded W   16 MB

// ---------------- acquire/release flag ops ----------------
__device__ __forceinline__ int ld_acq(const int* p) {
    int v;
    asm volatile("ld.acquire.gpu.global.s32 %0, [%1];" : "=r"(v) : "l"(p) : "memory");
    return v;
}
__device__ __forceinline__ void st_rel(int* p, int v) {
    asm volatile("st.release.gpu.global.s32 [%0], %1;" :: "l"(p), "r"(v) : "memory");
}

// ---------------- packed dual-fp32 FMA (recurrence) ----------------
__device__ __forceinline__ void ffma2(unsigned long long& d,
                                      unsigned long long a,
                                      unsigned long long b) {
    asm("fma.rn.f32x2 %0, %1, %2, %3;" : "=l"(d) : "l"(a), "l"(b), "l"(d));
}
__device__ __forceinline__ float pairsum(unsigned long long v) {
    return __uint_as_float((unsigned)(v & 0xffffffffull)) +
           __uint_as_float((unsigned)(v >> 32));
}

// ---------------- tf32 + cp.async helpers ----------------
__device__ __forceinline__ unsigned f2tf(float f) {
    unsigned u; asm("cvt.rna.tf32.f32 %0, %1;" : "=r"(u) : "f"(f)); return u;
}
__device__ __forceinline__ void mma_tf32(float* c, const unsigned* a, const unsigned* b) {
    asm volatile(
        "mma.sync.aligned.m16n8k8.row.col.f32.tf32.tf32.f32 "
        "{%0,%1,%2,%3}, {%4,%5,%6,%7}, {%8,%9}, {%0,%1,%2,%3};\n"
        : "+f"(c[0]), "+f"(c[1]), "+f"(c[2]), "+f"(c[3])
        : "r"(a[0]), "r"(a[1]), "r"(a[2]), "r"(a[3]), "r"(b[0]), "r"(b[1]));
}
__device__ __forceinline__ uint32_t smem_u32(const void* p) {
    uint32_t a;
    asm("{ .reg .u64 t; cvta.to.shared.u64 t, %1; cvt.u32.u64 %0, t; }"
        : "=r"(a) : "l"(p));
    return a;
}
__device__ __forceinline__ void cp16(uint32_t d, const void* s) {
    asm volatile("cp.async.cg.shared.global [%0], [%1], 16;" :: "r"(d), "l"(s));
}
__device__ __forceinline__ void cp_commit() {
    asm volatile("cp.async.commit_group;" ::: "memory");
}

// ---------------- prep: round fp32 -> tf32 ----------------
__global__ void cvt_tf32_kernel(const float* __restrict__ in,
                                float* __restrict__ out, int n4) {
    int i = blockIdx.x * blockDim.x + threadIdx.x;
    if (i >= n4) return;
    float4 v = *(const float4*)(in + (size_t)i * 4);
    v.x = __uint_as_float(f2tf(v.x));
    v.y = __uint_as_float(f2tf(v.y));
    v.z = __uint_as_float(f2tf(v.z));
    v.w = __uint_as_float(f2tf(v.w));
    *(float4*)(out + (size_t)i * 4) = v;
}

// ---------------- pack Wh [K=1024][4096] -> Wp[row][k] (recurrence) ----------------
__global__ void pack_wh_kernel(const float* __restrict__ Wh, float* __restrict__ Wp) {
    __shared__ float tile[32][33];
    const int c0 = blockIdx.x * 32;
    const int k0 = blockIdx.y * 32;
    const int tx = threadIdx.x, ty = threadIdx.y;
#pragma unroll
    for (int i = 0; i < 32; i += 8)
        tile[ty + i][tx] = Wh[(size_t)(k0 + ty + i) * G4H + c0 + tx];
    __syncthreads();
#pragma unroll
    for (int i = 0; i < 32; i += 8) {
        int c  = c0 + ty + i;
        int g  = c >> 10;
        int r  = c & (HN - 1);
        int row = ((r >> 3) << 5) + (g << 3) + (r & 7);
        Wp[(size_t)row * HN + k0 + tx] = tile[tx][ty + i];
    }
}

// ---------------- tf32 mma GEMM (unchanged, passing) ----------------
__global__ void __launch_bounds__(256, 2) gemm_xg_cp(
    const float* __restrict__ A, const float* __restrict__ Bw,
    const float* __restrict__ bias, float* __restrict__ C, int K)
{
    extern __shared__ char gsm[];
    const uint32_t sb = smem_u32(gsm);

    const int tid = threadIdx.x;
    const int bx = blockIdx.x;
    const int by = blockIdx.y;
    const int wid = tid >> 5;
    const int lane = tid & 31;
    const int g = lane >> 2, tg = lane & 3;
    const int wm = wid & 1, wn = wid >> 1;
    const int m0w = wm * 64, n0w = wn * 32;
    const int KT = K >> 5;

    const int aR = tid >> 3, aKc = tid & 7;
    const int bR = tid >> 5, bNc = tid & 31;

    float acc[4][4][4];
#pragma unroll
    for (int a = 0; a < 4; a++)
#pragma unroll
        for (int b = 0; b < 4; b++)
#pragma unroll
            for (int cix = 0; cix < 4; cix++) acc[a][b][cix] = 0.f;

    auto issue = [&](int kt, int buf) {
        const uint32_t as = sb + buf * STG;
        const uint32_t bs = as + ABYT;
#pragma unroll
        for (int it = 0; it < 4; it++) {
            int row = it * 32 + aR;
            uint32_t doff = row * 128 + ((aKc * 16) ^ ((row & 7) << 4));
            cp16(as + doff, A + (size_t)(by * 128 + row) * K + kt * 32 + aKc * 4);
        }
#pragma unroll
        for (int it = 0; it < 4; it++) {
            int kr = it * 8 + bR;
            cp16(bs + kr * 544 + bNc * 16,
                 Bw + (size_t)(kt * 32 + kr) * G4H + bx * 128 + bNc * 4);
        }
        cp_commit();
    };

    issue(0, 0);
    for (int kt = 0; kt < KT; kt++) {
        const int buf = kt & 1;
        if (kt + 1 < KT) {
            issue(kt + 1, (kt + 1) & 1);
            asm volatile("cp.async.wait_group 1;" ::: "memory");
        } else {
            asm volatile("cp.async.wait_group 0;" ::: "memory");
        }
        __syncthreads();

        const unsigned* As = (const unsigned*)(gsm + buf * STG);
        const unsigned* Bs = (const unsigned*)(gsm + buf * STG + ABYT);
#pragma unroll
        for (int s = 0; s < 4; s++) {
            unsigned af[4][4], bf[4][2];
            const int c0 = (8 * s + tg) ^ (g << 2);
            const int c1 = c0 ^ 4;
#pragma unroll
            for (int mb = 0; mb < 4; mb++) {
                int m = m0w + mb * 16 + g;
                af[mb][0] = As[m * 32 + c0];
                af[mb][1] = As[(m + 8) * 32 + c0];
                af[mb][2] = As[m * 32 + c1];
                af[mb][3] = As[(m + 8) * 32 + c1];
            }
#pragma unroll
            for (int nb = 0; nb < 4; nb++) {
                bf[nb][0] = Bs[(8 * s + tg) * 136 + n0w + nb * 8 + g];
                bf[nb][1] = Bs[(8 * s + tg + 4) * 136 + n0w + nb * 8 + g];
            }
#pragma unroll
            for (int mb = 0; mb < 4; mb++)
#pragma unroll
                for (int nb = 0; nb < 4; nb++)
                    mma_tf32(acc[mb][nb], af[mb], bf[nb]);
        }
        __syncthreads();
    }

#pragma unroll
    for (int mb = 0; mb < 4; mb++) {
        int m1 = by * 128 + m0w + mb * 16 + g;
        int m2 = m1 + 8;
        size_t r1 = (size_t)(((m1 & 511) << 5) + (m1 >> 9)) * G4H;
        size_t r2 = (size_t)(((m2 & 511) << 5) + (m2 >> 9)) * G4H;
#pragma unroll
        for (int nb = 0; nb < 4; nb++) {
            int n = bx * 128 + n0w + nb * 8 + 2 * tg;
            float2 bb = *(const float2*)(bias + n);
            float2 o1 = { acc[mb][nb][0] + bb.x, acc[mb][nb][1] + bb.y };
            float2 o2 = { acc[mb][nb][2] + bb.x, acc[mb][nb][3] + bb.y };
            *(float2*)(C + r1 + n) = o1;
            *(float2*)(C + r2 + n) = o2;
        }
    }
}

// ---------------- persistent LSTM layer: dataflow-flag sync (no grid barrier) ----------------
// 128 blocks x 512 threads. Block nb owns 8 n-cols (packed W rows nb*32..+32).
// Warp wq: ks = wq>>1 (k-slice), bh = wq&1 (batch half). Lane jj = gate-col.
// Sync: block nb publishes flag[nb]=t+1 (release) after writing its h(t) cols;
// consumers acquire all 128 flags >= t before staging h(t-1).  2-buffer safety:
// overwriting X at t+1 requires all flags >= t+1, which certifies every block
// finished reading X during step t.
extern __shared__ float s_mem[];
__global__ void __launch_bounds__(512, 1) lstm_layer_persistent(
    const float* __restrict__ xg, const float* __restrict__ Wp,
    float* __restrict__ hA, float* __restrict__ hB,
    float* __restrict__ outb, int* __restrict__ flg)
{
    const int tid = threadIdx.x;
    const int jj  = tid & 31;
    const int wq  = tid >> 5;        // 0..15
    const int ks  = wq >> 1;         // 0..7
    const int bh  = wq & 1;          // 0..1
    const int b0  = bh * 16;
    const int nb  = blockIdx.x;

    float* Wsm = s_mem;                       // 32 x WPAD
    float* hq0 = s_mem + 32 * WPAD;           // 32 x HQS (quarter ping)
    float* hq1 = hq0 + 32 * HQS;              // 32 x HQS (quarter pong)
    float* red = hq0;                         // [32][HQS] alias

    // ---- load this block's W slice into smem (once per layer) ----
    {
        const float4* Wg = (const float4*)(Wp + (size_t)nb * 32 * HN);
#pragma unroll
        for (int it = 0; it < 16; it++) {
            int i4  = it * 512 + tid;
            int row = i4 >> 8;
            int col = i4 & 255;
            *(float4*)(Wsm + (size_t)row * WPAD + col * 4) = Wg[i4];
        }
    }
    __syncthreads();

    const int nl  = tid & 7;
    const int myn = nb * 8 + nl;              // epilogue lane's output col
    const int myb = (tid >> 3) & 31;          // epilogue lane's batch (tid<256)
    float creg = 0.f;

    for (int t = 0; t < TLEN; t++) {
        const float* h_in  = (t & 1) ? hB : hA;
        float*       h_out = (t & 1) ? hA : hB;
        const float* xg_t  = xg + (size_t)t * BSZ * G4H;

        // ---- dataflow wait: all producers must have published step t-1 ----
        if (tid < NBLK) {
            while (ld_acq(&flg[tid]) < t) __nanosleep(32);
        }
        __syncthreads();   // also orders prev epilogue's red reads before STS(0)

        // epilogue lanes prefetch their 4 gate inputs
        float xvi = 0.f, xvf = 0.f, xvg = 0.f, xvo = 0.f;
        if (tid < 256) {
            const float* xp = xg_t + (size_t)myb * G4H + myn;
            xvi = xp[0];
            xvf = xp[HN];
            xvg = xp[2 * HN];
            xvo = xp[3 * HN];
        }

        unsigned long long acc2[16];
#pragma unroll
        for (int b = 0; b < 16; b++) acc2[b] = 0ull;

        // prefetch quarter 0 (L2 reads: h written by other SMs)
        float4 p[4];
#pragma unroll
        for (int i = 0; i < 4; i++) {
            int idx = i * 512 + tid;
            int b = idx >> 6, k4 = idx & 63;
            p[i] = __ldcg((const float4*)&h_in[(size_t)b * HN + k4 * 4]);
        }

#pragma unroll
        for (int q = 0; q < 4; q++) {
            float* hs = (q & 1) ? hq1 : hq0;
#pragma unroll
            for (int i = 0; i < 4; i++) {
                int idx = i * 512 + tid;
                int b = idx >> 6, k4 = idx & 63;
                *(float4*)&hs[b * HQS + k4 * 4] = p[i];
            }
            __syncthreads();
            if (q < 3) {
#pragma unroll
                for (int i = 0; i < 4; i++) {
                    int idx = i * 512 + tid;
                    int b = idx >> 6, k4 = idx & 63;
                    p[i] = __ldcg((const float4*)
                        &h_in[(size_t)b * HN + (q + 1) * 256 + k4 * 4]);
                }
            }
            const ulonglong2* Wk = (const ulonglong2*)
                (Wsm + (size_t)jj * WPAD + q * 256 + ks * 32);
            const char* hbase = (const char*)(hs + (size_t)b0 * HQS + ks * 32);
#pragma unroll
            for (int g = 0; g < 8; g++) {
                ulonglong2 wv = Wk[g];
                const char* hp = hbase + g * 16;
#pragma unroll
                for (int bb = 0; bb < 16; bb++) {
                    ulonglong2 hv = *(const ulonglong2*)(hp + bb * (HQS * 4));
                    ffma2(acc2[bb], wv.x, hv.x);
                    ffma2(acc2[bb], wv.y, hv.y);
                }
            }
        }

        // single-phase reduction store (red aliases hq0; safe, see R12 proof)
#pragma unroll
        for (int bb = 0; bb < 16; bb++)
            red[(size_t)(b0 + bb) * HQS + ks * 32 + jj] = pairsum(acc2[bb]);
        __syncthreads();

        if (tid < 256) {
            float gi = xvi, gf = xvf, gg = xvg, go = xvo;
#pragma unroll
            for (int s = 0; s < 8; s++) {
                const float* rp = &red[(size_t)myb * HQS + s * 32];
                gi += rp[nl];
                gf += rp[8 + nl];
                gg += rp[16 + nl];
                go += rp[24 + nl];
            }
            float si = 1.f / (1.f + expf(-gi));
            float sf = 1.f / (1.f + expf(-gf));
            float so = 1.f / (1.f + expf(-go));
            creg = sf * creg + si * tanhf(gg);
            float hv = so * tanhf(creg);
            h_out[(size_t)myb * HN + myn] = hv;
            outb[(size_t)myb * (TLEN * HN) + (size_t)t * HN + myn] = hv;
            __threadfence();   // make h_out visible before flag publish
        }
        __syncthreads();
        if (tid == 0) st_rel(&flg[nb], t + 1);
    }
}

// ---------------- driver ----------------
extern "C" void kernel_launch(void* const* d_in, const int* in_sizes, int n_in,
                              void* d_out, int out_size) {
    const float* x   = (const float*)d_in[0];
    const float* Wx0 = (const float*)d_in[1];
    const float* Wh0 = (const float*)d_in[2];
    const float* b0  = (const float*)d_in[3];
    const float* Wx1 = (const float*)d_in[4];
    const float* Wh1 = (const float*)d_in[5];
    const float* b1  = (const float*)d_in[6];
    float* out = (float*)d_out;

    float *xg, *hseq, *wp0, *wp1, *hbuf, *atf, *btf;
    int *flg0, *flg1;
    cudaGetSymbolAddress((void**)&xg,   g_xg);
    cudaGetSymbolAddress((void**)&hseq, g_hseq);
    cudaGetSymbolAddress((void**)&wp0,  g_Wp0);
    cudaGetSymbolAddress((void**)&wp1,  g_Wp1);
    cudaGetSymbolAddress((void**)&hbuf, g_h);
    cudaGetSymbolAddress((void**)&atf,  g_Atf);
    cudaGetSymbolAddress((void**)&btf,  g_Btf);
    cudaGetSymbolAddress((void**)&flg0, g_flag0);
    cudaGetSymbolAddress((void**)&flg1, g_flag1);

    const int SMEMB = (32 * WPAD + 2 * 32 * HQS) * (int)sizeof(float);
    cudaFuncSetAttribute(lstm_layer_persistent,
                         cudaFuncAttributeMaxDynamicSharedMemorySize, SMEMB);
    const int GSMEM = 2 * STG;
    cudaFuncSetAttribute(gemm_xg_cp,
                         cudaFuncAttributeMaxDynamicSharedMemorySize, GSMEM);

    const dim3 tpb(32, 8);

    // flags must start at 0 on every graph replay
    cudaMemsetAsync(flg0, 0, NBLK * sizeof(int), 0);
    cudaMemsetAsync(flg1, 0, NBLK * sizeof(int), 0);

    // capture-friendly order: cvtA(..), cvtW, pack0, gemm0, ...
    cvt_tf32_kernel<<<(16384 * DIN / 4 + 255) / 256, 256>>>(x, atf, 16384 * DIN / 4);
    cvt_tf32_kernel<<<(DIN * G4H / 4 + 255) / 256, 256>>>(Wx0, btf, DIN * G4H / 4);
    pack_wh_kernel<<<dim3(G4H / 32, HN / 32), tpb>>>(Wh0, wp0);
    gemm_xg_cp<<<dim3(G4H / 128, 16384 / 128), 256, GSMEM>>>(atf, btf, b0, xg, DIN);
    pack_wh_kernel<<<dim3(G4H / 32, HN / 32), tpb>>>(Wh1, wp1);
    cudaMemsetAsync(hbuf, 0, 2 * BSZ * HN * sizeof(float), 0);
    lstm_layer_persistent<<<NBLK, 512, SMEMB>>>(
        xg, wp0, hbuf, hbuf + BSZ * HN, hseq, flg0);

    // ---- layer 1 ----
    cvt_tf32_kernel<<<(16384 * HN / 4 + 255) / 256, 256>>>(hseq, atf, 16384 * HN / 4);
    cvt_tf32_kernel<<<(HN * G4H / 4 + 255) / 256, 256>>>(Wx1, btf, HN * G4H / 4);
    gemm_xg_cp<<<dim3(G4H / 128, 16384 / 128), 256, GSMEM>>>(atf, btf, b1, xg, HN);
    cudaMemsetAsync(hbuf, 0, 2 * BSZ * HN * sizeof(float), 0);
    lstm_layer_persistent<<<NBLK, 512, SMEMB>>>(
        xg, wp1, hbuf, hbuf + BSZ * HN, out, flg1);
}

// round 16
// speedup vs baseline: 2.1779x; 2.1779x over previous
#include <cuda_runtime.h>
#include <cuda_bf16.h>
#include <math.h>
#include <stdint.h>

// Problem dims (fixed)
#define BSZ  32
#define TLEN 512
#define DIN  512
#define HN   1024
#define G4H  (4*HN)   // 4096

#define NBLK 128       // persistent grid size (1 CTA/SM)

// recurrence smem layout
#define WWORDS   18432         // 512 kk-pairs x 36 (pad) u32 per split
#define WBYTES   (WWORDS*4)    // 73,728 B per split
#define HROW     264           // staged h row stride (bf16), pad 8
#define HSPLIT   (32*HROW*2)   // 16,896 B per split per buffer
#define STGB     (2*HSPLIT)    // 33,792 B per buffer (hi+lo)
#define SOFF     (2*WBYTES)    // staging offset = 147,456
#define RSMEMB   (SOFF + 2*STGB)  // 215,040 B total
#define REDS     260           // red row stride (floats)

// GEMM staging (bytes)
#define ABYT 16384     // As: 128 rows x 128B
#define BBYT 17408     // Bs: 32 rows x 544B (136 floats, pad 8)
#define STG  (ABYT + BBYT)

// ---------------- scratch (device globals; no allocation allowed) ----------------
__device__ float g_xg[(size_t)TLEN * BSZ * G4H];   // [T][B][4H]  256 MB
__device__ float g_hseq[(size_t)BSZ * TLEN * HN];  // [B][T][H]    64 MB
__device__ uint4 g_Wbh0[NBLK * 4608];              // packed Wh0 hi  9.4 MB
__device__ uint4 g_Wbl0[NBLK * 4608];              // packed Wh0 lo
__device__ uint4 g_Wbh1[NBLK * 4608];              // packed Wh1 hi
__device__ uint4 g_Wbl1[NBLK * 4608];              // packed Wh1 lo
__device__ uint4 g_hb4[2 * 2 * 4096];              // h bf16 [buf][split][32*1024]
__device__ unsigned g_cnt;
__device__ volatile unsigned g_gen;
__device__ float g_Atf[(size_t)16384 * 1024];      // tf32-rounded A   64 MB
__device__ float g_Btf[(size_t)1024 * G4H];        // tf32-rounded W   16 MB

// ---------------- grid-wide barrier (R5-proven) ----------------
__device__ __forceinline__ void grid_bar() {
    __threadfence();
    __syncthreads();
    if (threadIdx.x == 0) {
        unsigned my = g_gen;
        if (atomicAdd(&g_cnt, 1u) == (unsigned)(gridDim.x - 1)) {
            g_cnt = 0;
            __threadfence();
            g_gen = my + 1;
        } else {
            while (g_gen == my) { }
        }
        __threadfence();
    }
    __syncthreads();
}

// ---------------- mma helpers ----------------
__device__ __forceinline__ void mma_bf16(float* c, const unsigned* a, const unsigned* b) {
    asm volatile(
        "mma.sync.aligned.m16n8k16.row.col.f32.bf16.bf16.f32 "
        "{%0,%1,%2,%3}, {%4,%5,%6,%7}, {%8,%9}, {%0,%1,%2,%3};\n"
        : "+f"(c[0]), "+f"(c[1]), "+f"(c[2]), "+f"(c[3])
        : "r"(a[0]), "r"(a[1]), "r"(a[2]), "r"(a[3]), "r"(b[0]), "r"(b[1]));
}
__device__ __forceinline__ unsigned f2tf(float f) {
    unsigned u; asm("cvt.rna.tf32.f32 %0, %1;" : "=r"(u) : "f"(f)); return u;
}
__device__ __forceinline__ void mma_tf32(float* c, const unsigned* a, const unsigned* b) {
    asm volatile(
        "mma.sync.aligned.m16n8k8.row.col.f32.tf32.tf32.f32 "
        "{%0,%1,%2,%3}, {%4,%5,%6,%7}, {%8,%9}, {%0,%1,%2,%3};\n"
        : "+f"(c[0]), "+f"(c[1]), "+f"(c[2]), "+f"(c[3])
        : "r"(a[0]), "r"(a[1]), "r"(a[2]), "r"(a[3]), "r"(b[0]), "r"(b[1]));
}
__device__ __forceinline__ uint32_t smem_u32(const void* p) {
    uint32_t a;
    asm("{ .reg .u64 t; cvta.to.shared.u64 t, %1; cvt.u32.u64 %0, t; }"
        : "=r"(a) : "l"(p));
    return a;
}
__device__ __forceinline__ void cp16(uint32_t d, const void* s) {
    asm volatile("cp.async.cg.shared.global [%0], [%1], 16;" :: "r"(d), "l"(s));
}
__device__ __forceinline__ void cp_commit() {
    asm volatile("cp.async.commit_group;" ::: "memory");
}

// ---------------- prep: round fp32 -> tf32 ----------------
__global__ void cvt_tf32_kernel(const float* __restrict__ in,
                                float* __restrict__ out, int n4) {
    int i = blockIdx.x * blockDim.x + threadIdx.x;
    if (i >= n4) return;
    float4 v = *(const float4*)(in + (size_t)i * 4);
    v.x = __uint_as_float(f2tf(v.x));
    v.y = __uint_as_float(f2tf(v.y));
    v.z = __uint_as_float(f2tf(v.z));
    v.w = __uint_as_float(f2tf(v.w));
    *(float4*)(out + (size_t)i * 4) = v;
}

// ---------------- prep: pack Wh -> bf16 hi/lo k-pair-interleaved ----------------
// Block nb's W slice: packed col nl = gate*8 + r_local, gate-major; word [kk][nl]
// = { bf16(W[2kk][col]) lo-half, bf16(W[2kk+1][col]) hi-half }, stride 36.
__global__ void pack_whb_kernel(const float* __restrict__ Wh,
                                uint4* __restrict__ whi, uint4* __restrict__ wlo) {
    const int nb = blockIdx.x;
    const int tid = threadIdx.x;
    uint32_t* Hi = (uint32_t*)(whi + (size_t)nb * 4608);
    uint32_t* Lo = (uint32_t*)(wlo + (size_t)nb * 4608);
#pragma unroll 4
    for (int e = 0; e < 64; e++) {
        int idx = e * 256 + tid;          // 0..16383
        int kk = idx >> 5;                // 0..511
        int nl = idx & 31;
        int col = ((nl >> 3) << 10) + nb * 8 + (nl & 7);
        float w0 = Wh[(size_t)(2 * kk) * G4H + col];
        float w1 = Wh[(size_t)(2 * kk + 1) * G4H + col];
        __nv_bfloat16 h0 = __float2bfloat16_rn(w0);
        __nv_bfloat16 h1 = __float2bfloat16_rn(w1);
        __nv_bfloat16 l0 = __float2bfloat16_rn(w0 - __bfloat162float(h0));
        __nv_bfloat16 l1 = __float2bfloat16_rn(w1 - __bfloat162float(h1));
        __nv_bfloat162 ph; ph.x = h0; ph.y = h1;
        __nv_bfloat162 pl; pl.x = l0; pl.y = l1;
        Hi[kk * 36 + nl] = *(uint32_t*)&ph;
        Lo[kk * 36 + nl] = *(uint32_t*)&pl;
    }
}

// ---------------- tf32 mma GEMM (unchanged, passing) ----------------
__global__ void __launch_bounds__(256, 2) gemm_xg_cp(
    const float* __restrict__ A, const float* __restrict__ Bw,
    const float* __restrict__ bias, float* __restrict__ C, int K)
{
    extern __shared__ char gsm[];
    const uint32_t sb = smem_u32(gsm);

    const int tid = threadIdx.x;
    const int bx = blockIdx.x;
    const int by = blockIdx.y;
    const int wid = tid >> 5;
    const int lane = tid & 31;
    const int g = lane >> 2, tg = lane & 3;
    const int wm = wid & 1, wn = wid >> 1;
    const int m0w = wm * 64, n0w = wn * 32;
    const int KT = K >> 5;

    const int aR = tid >> 3, aKc = tid & 7;
    const int bR = tid >> 5, bNc = tid & 31;

    float acc[4][4][4];
#pragma unroll
    for (int a = 0; a < 4; a++)
#pragma unroll
        for (int b = 0; b < 4; b++)
#pragma unroll
            for (int cix = 0; cix < 4; cix++) acc[a][b][cix] = 0.f;

    auto issue = [&](int kt, int buf) {
        const uint32_t as = sb + buf * STG;
        const uint32_t bs = as + ABYT;
#pragma unroll
        for (int it = 0; it < 4; it++) {
            int row = it * 32 + aR;
            uint32_t doff = row * 128 + ((aKc * 16) ^ ((row & 7) << 4));
            cp16(as + doff, A + (size_t)(by * 128 + row) * K + kt * 32 + aKc * 4);
        }
#pragma unroll
        for (int it = 0; it < 4; it++) {
            int kr = it * 8 + bR;
            cp16(bs + kr * 544 + bNc * 16,
                 Bw + (size_t)(kt * 32 + kr) * G4H + bx * 128 + bNc * 4);
        }
        cp_commit();
    };

    issue(0, 0);
    for (int kt = 0; kt < KT; kt++) {
        const int buf = kt & 1;
        if (kt + 1 < KT) {
            issue(kt + 1, (kt + 1) & 1);
            asm volatile("cp.async.wait_group 1;" ::: "memory");
        } else {
            asm volatile("cp.async.wait_group 0;" ::: "memory");
        }
        __syncthreads();

        const unsigned* As = (const unsigned*)(gsm + buf * STG);
        const unsigned* Bs = (const unsigned*)(gsm + buf * STG + ABYT);
#pragma unroll
        for (int s = 0; s < 4; s++) {
            unsigned af[4][4], bf[4][2];
            const int c0 = (8 * s + tg) ^ (g << 2);
            const int c1 = c0 ^ 4;
#pragma unroll
            for (int mb = 0; mb < 4; mb++) {
                int m = m0w + mb * 16 + g;
                af[mb][0] = As[m * 32 + c0];
                af[mb][1] = As[(m + 8) * 32 + c0];
                af[mb][2] = As[m * 32 + c1];
                af[mb][3] = As[(m + 8) * 32 + c1];
            }
#pragma unroll
            for (int nb = 0; nb < 4; nb++) {
                bf[nb][0] = Bs[(8 * s + tg) * 136 + n0w + nb * 8 + g];
                bf[nb][1] = Bs[(8 * s + tg + 4) * 136 + n0w + nb * 8 + g];
            }
#pragma unroll
            for (int mb = 0; mb < 4; mb++)
#pragma unroll
                for (int nb = 0; nb < 4; nb++)
                    mma_tf32(acc[mb][nb], af[mb], bf[nb]);
        }
        __syncthreads();
    }

#pragma unroll
    for (int mb = 0; mb < 4; mb++) {
        int m1 = by * 128 + m0w + mb * 16 + g;
        int m2 = m1 + 8;
        size_t r1 = (size_t)(((m1 & 511) << 5) + (m1 >> 9)) * G4H;
        size_t r2 = (size_t)(((m2 & 511) << 5) + (m2 >> 9)) * G4H;
#pragma unroll
        for (int nb = 0; nb < 4; nb++) {
            int n = bx * 128 + n0w + nb * 8 + 2 * tg;
            float2 bb = *(const float2*)(bias + n);
            float2 o1 = { acc[mb][nb][0] + bb.x, acc[mb][nb][1] + bb.y };
            float2 o2 = { acc[mb][nb][2] + bb.x, acc[mb][nb][3] + bb.y };
            *(float2*)(C + r1 + n) = o1;
            *(float2*)(C + r2 + n) = o2;
        }
    }
}

// ---------------- persistent LSTM layer: bf16-split mma.sync recurrence ----------------
// 128 blocks x 256 threads (8 warps). Block nb owns 32 gate-cols (8 n-cols).
// Per step: D[32 b][32 n] = h[32 b][1024 k] @ W[1024 k][32 n] via m16n8k16 bf16,
// 3 split terms (hh + hl + lh), fp32 accum. Warp wq owns k-slice of 128
// (2 k16-chunks per k256 quarter). Cross-warp reduce via smem red (aliased on
// staging buf0), epilogue fuses gates + cell update; h published as bf16 hi/lo.
extern __shared__ char r_smem[];
__global__ void __launch_bounds__(256, 1) lstm_layer_persistent(
    const float* __restrict__ xg,
    const uint4* __restrict__ whi, const uint4* __restrict__ wlo,
    __nv_bfloat16* __restrict__ hb, float* __restrict__ outb)
{
    const int tid  = threadIdx.x;
    const int lane = tid & 31;
    const int wq   = tid >> 5;        // 0..7 (k-slice)
    const int g    = lane >> 2;       // 0..7
    const int t4   = lane & 3;        // 0..3
    const int nb   = blockIdx.x;

    uint32_t* Wshi = (uint32_t*)r_smem;            // [512][36] u32
    uint32_t* Wslo = Wshi + WWORDS;
    char*     stg0 = r_smem + SOFF;                // staging buf0 (hi | lo)
    char*     stg1 = stg0 + STGB;                  // staging buf1
    float*    red  = (float*)stg0;                 // [32 b][REDS] alias

    // ---- load W hi/lo into smem (once per layer) ----
    {
        const uint4* Gh = whi + (size_t)nb * 4608;
        const uint4* Gl = wlo + (size_t)nb * 4608;
        uint4* Sh = (uint4*)Wshi;
        uint4* Sl = (uint4*)Wslo;
#pragma unroll
        for (int it = 0; it < 18; it++) {
            Sh[it * 256 + tid] = Gh[it * 256 + tid];
            Sl[it * 256 + tid] = Gl[it * 256 + tid];
        }
    }
    __syncthreads();

    const int nl  = tid & 7;
    const int myn = nb * 8 + nl;              // epilogue lane's output col
    const int myb = (tid >> 3) & 31;          // epilogue lane's batch
    float creg = 0.f;

    for (int t = 0; t < TLEN; t++) {
        const int inb = t & 1, outbuf = inb ^ 1;
        const __nv_bfloat16* hinH = hb + inb * 65536;
        const __nv_bfloat16* hinL = hinH + 32768;
        __nv_bfloat16* houtH = hb + outbuf * 65536;
        __nv_bfloat16* houtL = houtH + 32768;
        const float* xg_t = xg + (size_t)t * BSZ * G4H;

        // prefetch this lane's 4 gate inputs (DRAM; hidden under compute)
        const float* xp = xg_t + (size_t)myb * G4H + myn;
        float xvi = xp[0];
        float xvf = xp[HN];
        float xvg = xp[2 * HN];
        float xvo = xp[3 * HN];

        float acc[2][4][4];
#pragma unroll
        for (int mt = 0; mt < 2; mt++)
#pragma unroll
            for (int nt = 0; nt < 4; nt++)
#pragma unroll
                for (int i = 0; i < 4; i++) acc[mt][nt][i] = 0.f;

        // prefetch quarter 0 (uint4 = 8 bf16); L2 reads (h written by other SMs)
        uint4 ph[4], pl[4];
#pragma unroll
        for (int it = 0; it < 4; it++) {
            int j = it * 256 + tid;
            int b = j >> 5, k8 = j & 31;
            ph[it] = __ldcg((const uint4*)hinH + b * 128 + k8);
            pl[it] = __ldcg((const uint4*)hinL + b * 128 + k8);
        }

#pragma unroll
        for (int q = 0; q < 4; q++) {
            char* sb = (q & 1) ? stg1 : stg0;
#pragma unroll
            for (int it = 0; it < 4; it++) {
                int j = it * 256 + tid;
                int b = j >> 5, k8 = j & 31;
                *(uint4*)(sb + b * 528 + k8 * 16) = ph[it];
                *(uint4*)(sb + HSPLIT + b * 528 + k8 * 16) = pl[it];
            }
            __syncthreads();
            if (q < 3) {
#pragma unroll
                for (int it = 0; it < 4; it++) {
                    int j = it * 256 + tid;
                    int b = j >> 5, k8 = j & 31;
                    ph[it] = __ldcg((const uint4*)hinH + b * 128 + (q + 1) * 32 + k8);
                    pl[it] = __ldcg((const uint4*)hinL + b * 128 + (q + 1) * 32 + k8);
                }
            }
            const __nv_bfloat16* shH = (const __nv_bfloat16*)sb;
            const __nv_bfloat16* shL = (const __nv_bfloat16*)(sb + HSPLIT);
#pragma unroll
            for (int c = 0; c < 2; c++) {
                const int kc  = wq * 32 + c * 16;          // bf16 col in quarter
                const int kkb = q * 128 + wq * 16 + c * 8; // global k-pair base
                unsigned ahi[2][4], alo[2][4];
                const int ab = kc + 2 * t4;
#pragma unroll
                for (int mt = 0; mt < 2; mt++) {
                    int r0 = mt * 16 + g;
                    const __nv_bfloat16* pH = shH + r0 * HROW + ab;
                    const __nv_bfloat16* pL = shL + r0 * HROW + ab;
                    ahi[mt][0] = *(const uint32_t*)(pH);
                    ahi[mt][1] = *(const uint32_t*)(pH + 8 * HROW);
                    ahi[mt][2] = *(const uint32_t*)(pH + 8);
                    ahi[mt][3] = *(const uint32_t*)(pH + 8 * HROW + 8);
                    alo[mt][0] = *(const uint32_t*)(pL);
                    alo[mt][1] = *(const uint32_t*)(pL + 8 * HROW);
                    alo[mt][2] = *(const uint32_t*)(pL + 8);
                    alo[mt][3] = *(const uint32_t*)(pL + 8 * HROW + 8);
                }
#pragma unroll
                for (int nt = 0; nt < 4; nt++) {
                    const uint32_t* wh = Wshi + (kkb + t4) * 36 + nt * 8 + g;
                    const uint32_t* wl = Wslo + (kkb + t4) * 36 + nt * 8 + g;
                    unsigned bhi[2] = { wh[0], wh[4 * 36] };
                    unsigned blo[2] = { wl[0], wl[4 * 36] };
#pragma unroll
                    for (int mt = 0; mt < 2; mt++) {
                        mma_bf16(acc[mt][nt], ahi[mt], bhi);
                        mma_bf16(acc[mt][nt], ahi[mt], blo);
                        mma_bf16(acc[mt][nt], alo[mt], bhi);
                    }
                }
            }
        }

        // ---- cross-warp reduction: write fragments to red[b][wq*32 + ncol] ----
        // (red aliases buf0: q2 was the last buf0 compute, ordered before q3's sync)
#pragma unroll
        for (int mt = 0; mt < 2; mt++) {
            int b1 = mt * 16 + g;
#pragma unroll
            for (int nt = 0; nt < 4; nt++) {
                int ncol = wq * 32 + nt * 8 + 2 * t4;
                float2 v1 = { acc[mt][nt][0], acc[mt][nt][1] };
                float2 v2 = { acc[mt][nt][2], acc[mt][nt][3] };
                *(float2*)&red[(size_t)b1 * REDS + ncol] = v1;
                *(float2*)&red[(size_t)(b1 + 8) * REDS + ncol] = v2;
            }
        }
        __syncthreads();

        // ---- epilogue: sum 8 k-slices, gates, cell update, publish h ----
        {
            float gi = xvi, gf = xvf, gg = xvg, go = xvo;
#pragma unroll
            for (int s = 0; s < 8; s++) {
                const float* rp = &red[(size_t)myb * REDS + s * 32];
                gi += rp[nl];
                gf += rp[8 + nl];
                gg += rp[16 + nl];
                go += rp[24 + nl];
            }
            float si = 1.f / (1.f + expf(-gi));
            float sf = 1.f / (1.f + expf(-gf));
            float so = 1.f / (1.f + expf(-go));
            creg = sf * creg + si * tanhf(gg);
            float hv = so * tanhf(creg);

            __nv_bfloat16 hhi = __float2bfloat16_rn(hv);
            __nv_bfloat16 hlo = __float2bfloat16_rn(hv - __bfloat162float(hhi));
            houtH[(size_t)myb * HN + myn] = hhi;
            houtL[(size_t)myb * HN + myn] = hlo;
            outb[(size_t)myb * (TLEN * HN) + (size_t)t * HN + myn] = hv;
        }

        grid_bar();   // includes threadfence: h publish ordered before release
    }
}

// ---------------- driver ----------------
extern "C" void kernel_launch(void* const* d_in, const int* in_sizes, int n_in,
                              void* d_out, int out_size) {
    const float* x   = (const float*)d_in[0];
    const float* Wx0 = (const float*)d_in[1];
    const float* Wh0 = (const float*)d_in[2];
    const float* b0  = (const float*)d_in[3];
    const float* Wx1 = (const float*)d_in[4];
    const float* Wh1 = (const float*)d_in[5];
    const float* b1  = (const float*)d_in[6];
    float* out = (float*)d_out;

    float *xg, *hseq, *atf, *btf;
    uint4 *wbh0, *wbl0, *wbh1, *wbl1, *hb4;
    cudaGetSymbolAddress((void**)&xg,   g_xg);
    cudaGetSymbolAddress((void**)&hseq, g_hseq);
    cudaGetSymbolAddress((void**)&atf,  g_Atf);
    cudaGetSymbolAddress((void**)&btf,  g_Btf);
    cudaGetSymbolAddress((void**)&wbh0, g_Wbh0);
    cudaGetSymbolAddress((void**)&wbl0, g_Wbl0);
    cudaGetSymbolAddress((void**)&wbh1, g_Wbh1);
    cudaGetSymbolAddress((void**)&wbl1, g_Wbl1);
    cudaGetSymbolAddress((void**)&hb4,  g_hb4);

    cudaFuncSetAttribute(lstm_layer_persistent,
                         cudaFuncAttributeMaxDynamicSharedMemorySize, RSMEMB);
    const int GSMEM = 2 * STG;
    cudaFuncSetAttribute(gemm_xg_cp,
                         cudaFuncAttributeMaxDynamicSharedMemorySize, GSMEM);

    // capture-friendly order: cvtA(1), cvtW(2), pack0(3), gemm0(4), ...
    cvt_tf32_kernel<<<(16384 * DIN / 4 + 255) / 256, 256>>>(x, atf, 16384 * DIN / 4);
    cvt_tf32_kernel<<<(DIN * G4H / 4 + 255) / 256, 256>>>(Wx0, btf, DIN * G4H / 4);
    pack_whb_kernel<<<NBLK, 256>>>(Wh0, wbh0, wbl0);
    gemm_xg_cp<<<dim3(G4H / 128, 16384 / 128), 256, GSMEM>>>(atf, btf, b0, xg, DIN);
    pack_whb_kernel<<<NBLK, 256>>>(Wh1, wbh1, wbl1);
    cudaMemsetAsync(hb4, 0, 2 * 2 * 4096 * sizeof(uint4), 0);
    lstm_layer_persistent<<<NBLK, 256, RSMEMB>>>(
        xg, wbh0, wbl0, (__nv_bfloat16*)hb4, hseq);

    // ---- layer 1 ----
    cvt_tf32_kernel<<<(16384 * HN / 4 + 255) / 256, 256>>>(hseq, atf, 16384 * HN / 4);
    cvt_tf32_kernel<<<(HN * G4H / 4 + 255) / 256, 256>>>(Wx1, btf, HN * G4H / 4);
    gemm_xg_cp<<<dim3(G4H / 128, 16384 / 128), 256, GSMEM>>>(atf, btf, b1, xg, HN);
    cudaMemsetAsync(hb4, 0, 2 * 2 * 4096 * sizeof(uint4), 0);
    lstm_layer_persistent<<<NBLK, 256, RSMEMB>>>(
        xg, wbh1, wbl1, (__nv_bfloat16*)hb4, out);
}